// round 1
// baseline (speedup 1.0000x reference)
#include <cuda_runtime.h>
#include <cuda_bf16.h>
#include <cstdint>

// ---------------------------------------------------------------------------
// Problem constants
// ---------------------------------------------------------------------------
#define NN     32
#define BB     16384
#define SD     128
#define AD     64
#define AD2    64
#define IDIM   (SD + AD)        // 192
#define HH     256
#define HEADS  4
#define AT     64               // H / HEADS
#define ODIM   64
#define NOTH   (NN - 1)         // 31 "others"

// ---------------------------------------------------------------------------
// Scratch (no cudaMalloc allowed -> __device__ globals)
// ---------------------------------------------------------------------------
__device__ float g_SA  [(long)NOTH * BB * HH];        // sa[1..31]           520 MB
__device__ float g_KV  [(long)NOTH * BB * 2 * HH];    // keys|vals per row  1040 MB
__device__ float g_SENC[(long)BB * HH];               // s_enc               16 MB
__device__ float g_SEL [(long)BB * HH];               // sel (b, e*64+d)     16 MB
__device__ float g_CRIT[(long)BB * 4 * HH];           // critic_in           64 MB
__device__ float g_H1  [(long)BB * HH];               // h1                  16 MB
__device__ float g_WKV [HH * 2 * HH];                 // packed [h][c] c=key|val
__device__ float g_WSEL[HH * HH];                     // packed [h][e*64+d]
__device__ float g_BKV [2 * HH];                      // 0.. | bv

// ---------------------------------------------------------------------------
// Weight packing:  Wk/Wv/Wsel are (HEADS, H, AT) -> [h][e*64+d]
// ---------------------------------------------------------------------------
__global__ void pack_kernel(const float* __restrict__ Wk,
                            const float* __restrict__ Wv,
                            const float* __restrict__ bv,
                            const float* __restrict__ Wsel)
{
    int i = blockIdx.x * blockDim.x + threadIdx.x;   // 0 .. 65535
    if (i < HH * HH) {
        int h = i >> 8;
        int c = i & 255;
        int e = c >> 6;
        int d = c & 63;
        long src = ((long)e * HH + h) * AT + d;
        g_WKV[h * 512 + c]        = Wk[src];
        g_WKV[h * 512 + 256 + c]  = Wv[src];
        g_WSEL[h * 256 + c]       = Wsel[src];
    }
    if (i < 512) g_BKV[i] = (i < 256) ? 0.f : bv[i - 256];
}

// ---------------------------------------------------------------------------
// Generic tiled SGEMM:  C[M,N] = act( A[M,K] @ W[K,N] + bias )
//   - row-major A, W, C
//   - lrelu applied to columns  col >= act_from   (act_from = 0 -> all,
//     act_from = N -> none, act_from = 256 -> vals half only)
//   - optional second output C2
//   - batched via blockIdx.z with element strides
// Requirements: M % BM == 0, N % BN == 0, K % BK == 0 (all shapes here comply)
// ---------------------------------------------------------------------------
template <int BM, int BN, int BK, int TM, int TN>
__global__ void __launch_bounds__((BM / TM) * (BN / TN))
sgemm_kernel(const float* __restrict__ A,
             const float* __restrict__ W,
             const float* __restrict__ bias,
             float* __restrict__ C, int ldc,
             float* __restrict__ C2, int ldc2,
             int M, int N, int K, int act_from,
             long strideA, long strideW, long strideBias, long strideC)
{
    constexpr int THREADS = (BM / TM) * (BN / TN);
    static_assert(BM * BK / 4 == THREADS, "A tile loader mapping");
    static_assert(BK * BN / 4 == THREADS, "B tile loader mapping");

    const int t  = threadIdx.x;
    const int bz = blockIdx.z;

    A += (long)bz * strideA;
    W += (long)bz * strideW;
    if (bias) bias += (long)bz * strideBias;
    C += (long)bz * strideC;

    const int rowBase = blockIdx.y * BM;
    const int colBase = blockIdx.x * BN;

    __shared__ __align__(16) float As[BK][BM];
    __shared__ __align__(16) float Bs[BK][BN];

    // tile loader indices (1 float4 per thread per tile)
    const int a_row = t / (BK / 4);
    const int a_seg = t % (BK / 4);
    const int b_k   = t / (BN / 4);
    const int b_col = t % (BN / 4);

    const int tx = t % (BN / TN);
    const int ty = t / (BN / TN);

    float acc[TM][TN];
#pragma unroll
    for (int i = 0; i < TM; i++)
#pragma unroll
        for (int j = 0; j < TN; j++) acc[i][j] = 0.f;

    const float* Aptr = A + (long)(rowBase + a_row) * K + a_seg * 4;
    const float* Wptr = W + (long)b_k * N + colBase + b_col * 4;

    float4 aReg = *(const float4*)Aptr;
    float4 bReg = *(const float4*)Wptr;

    const int nChunks = K / BK;
    for (int c = 0; c < nChunks; c++) {
        As[a_seg * 4 + 0][a_row] = aReg.x;
        As[a_seg * 4 + 1][a_row] = aReg.y;
        As[a_seg * 4 + 2][a_row] = aReg.z;
        As[a_seg * 4 + 3][a_row] = aReg.w;
        *(float4*)&Bs[b_k][b_col * 4] = bReg;
        __syncthreads();

        if (c + 1 < nChunks) {   // prefetch next tile while computing this one
            aReg = *(const float4*)(Aptr + (long)(c + 1) * BK);
            bReg = *(const float4*)(Wptr + (long)(c + 1) * BK * N);
        }

#pragma unroll
        for (int k = 0; k < BK; k++) {
            float a[TM], b[TN];
#pragma unroll
            for (int i = 0; i < TM; i += 4)
                *(float4*)&a[i] = *(const float4*)&As[k][ty * TM + i];
#pragma unroll
            for (int j = 0; j < TN; j += 4)
                *(float4*)&b[j] = *(const float4*)&Bs[k][tx * TN + j];
#pragma unroll
            for (int i = 0; i < TM; i++)
#pragma unroll
                for (int j = 0; j < TN; j++)
                    acc[i][j] += a[i] * b[j];
        }
        __syncthreads();
    }

    // epilogue
#pragma unroll
    for (int i = 0; i < TM; i++) {
        const long r = rowBase + ty * TM + i;
#pragma unroll
        for (int j = 0; j < TN; j++) {
            const int col = colBase + tx * TN + j;
            float v = acc[i][j] + (bias ? bias[col] : 0.f);
            if (col >= act_from) v = (v > 0.f) ? v : 0.01f * v;
            C[r * ldc + col] = v;
            if (C2) C2[r * ldc2 + col] = v;
        }
    }
}

// ---------------------------------------------------------------------------
// Attention: one warp per (head e, batch b).
// KV layout: KV[n][b][0:256]=keys(e*64+d), [256:512]=vals(e*64+d)
// logits[n] = (sel . keys[n]) / 8 ; softmax over 31 ; out = sum w[n]*vals[n]
// Writes other_flat into CRIT columns 768..1023.
// ---------------------------------------------------------------------------
__global__ void attention_kernel(const float* __restrict__ SEL,
                                 const float* __restrict__ KV,
                                 float* __restrict__ CRIT)
{
    const int warp = (blockIdx.x * blockDim.x + threadIdx.x) >> 5;
    const int lane = threadIdx.x & 31;
    const int e = warp & 3;
    const int b = warp >> 2;

    const float2 s = *(const float2*)&SEL[(long)b * 256 + e * 64 + lane * 2];

    float logits[NOTH];
#pragma unroll
    for (int n = 0; n < NOTH; n++) {
        const float2 kv =
            *(const float2*)&KV[((long)n * BB + b) * 512 + e * 64 + lane * 2];
        float p = kv.x * s.x + kv.y * s.y;
#pragma unroll
        for (int o = 16; o > 0; o >>= 1)
            p += __shfl_xor_sync(0xffffffffu, p, o);
        logits[n] = p * 0.125f;      // / sqrt(AT=64)
    }

    float m = logits[0];
#pragma unroll
    for (int n = 1; n < NOTH; n++) m = fmaxf(m, logits[n]);

    float sum = 0.f;
#pragma unroll
    for (int n = 0; n < NOTH; n++) {
        logits[n] = __expf(logits[n] - m);
        sum += logits[n];
    }
    const float inv = 1.f / sum;

    float2 acc = make_float2(0.f, 0.f);
#pragma unroll
    for (int n = 0; n < NOTH; n++) {
        const float2 v =
            *(const float2*)&KV[((long)n * BB + b) * 512 + 256 + e * 64 + lane * 2];
        const float w = logits[n] * inv;
        acc.x += w * v.x;
        acc.y += w * v.y;
    }

    *(float2*)&CRIT[(long)b * 1024 + 768 + e * 64 + lane * 2] = acc;
}

// ---------------------------------------------------------------------------
// Launch
// ---------------------------------------------------------------------------
extern "C" void kernel_launch(void* const* d_in, const int* in_sizes, int n_in,
                              void* d_out, int out_size)
{
    const float* agent = (const float*)d_in[0];   // (32, 16384, 192)
    const float* state = (const float*)d_in[1];   // (16384, 128)
    const float* mf    = (const float*)d_in[2];   // (16384, 64)
    const float* mf2   = (const float*)d_in[3];   // (16384, 64)
    const float* encW  = (const float*)d_in[4];   // (32, 192, 256)
    const float* encB  = (const float*)d_in[5];   // (32, 256)
    const float* sW    = (const float*)d_in[6];   // (128, 256)
    const float* sb    = (const float*)d_in[7];   // (256)
    const float* mfW   = (const float*)d_in[8];   // (64, 256)
    const float* mfb   = (const float*)d_in[9];   // (256)
    const float* mf2W  = (const float*)d_in[10];  // (64, 256)
    const float* mf2b  = (const float*)d_in[11];  // (256)
    const float* Wk    = (const float*)d_in[12];  // (4, 256, 64)
    const float* Wsel  = (const float*)d_in[13];  // (4, 256, 64)
    const float* Wv    = (const float*)d_in[14];  // (4, 256, 64)
    const float* bv    = (const float*)d_in[15];  // (4, 64)
    const float* W1    = (const float*)d_in[16];  // (1024, 256)
    const float* b1    = (const float*)d_in[17];  // (256)
    const float* W2    = (const float*)d_in[18];  // (256, 64)
    const float* b2    = (const float*)d_in[19];  // (64)
    float* out = (float*)d_out;                   // (16384, 64)

    float *SA, *KV, *SENC, *SEL, *CRIT, *H1, *WKV, *WSEL, *BKV;
    cudaGetSymbolAddress((void**)&SA,   g_SA);
    cudaGetSymbolAddress((void**)&KV,   g_KV);
    cudaGetSymbolAddress((void**)&SENC, g_SENC);
    cudaGetSymbolAddress((void**)&SEL,  g_SEL);
    cudaGetSymbolAddress((void**)&CRIT, g_CRIT);
    cudaGetSymbolAddress((void**)&H1,   g_H1);
    cudaGetSymbolAddress((void**)&WKV,  g_WKV);
    cudaGetSymbolAddress((void**)&WSEL, g_WSEL);
    cudaGetSymbolAddress((void**)&BKV,  g_BKV);

    // 0) pack attention weights
    pack_kernel<<<256, 256>>>(Wk, Wv, bv, Wsel);

    // 1) encoder for n = 1..31 (sa[0] is never used):
    //    SA[n-1] = lrelu(agent[n] @ encW[n] + encB[n]),  [16384 x 256]
    {
        dim3 grid(HH / 128, BB / 128, NOTH);
        sgemm_kernel<128, 128, 8, 8, 8><<<grid, 256>>>(
            agent + (long)BB * IDIM, encW + (long)IDIM * HH, encB + HH,
            SA, HH, nullptr, 0,
            BB, HH, IDIM, /*act_from=*/0,
            (long)BB * IDIM, (long)IDIM * HH, HH, (long)BB * HH);
    }

    // 2) keys|vals: KV = SA @ WKV (+BKV, lrelu on cols >= 256)
    //    M = 31*16384 = 507904, K = 256, N = 512
    {
        dim3 grid(512 / 128, (NOTH * BB) / 128, 1);
        sgemm_kernel<128, 128, 8, 8, 8><<<grid, 256>>>(
            SA, WKV, BKV,
            KV, 512, nullptr, 0,
            NOTH * BB, 512, HH, /*act_from=*/256,
            0, 0, 0, 0);
    }

    // 3) small encoders -> CRIT columns, s_enc also into SENC
    {
        dim3 grid(HH / 128, BB / 128, 1);
        // s_enc -> CRIT[:,0:256] and SENC
        sgemm_kernel<128, 128, 8, 8, 8><<<grid, 256>>>(
            state, sW, sb, CRIT + 0, 1024, SENC, 256,
            BB, HH, SD, 0, 0, 0, 0, 0);
        // mf_enc -> CRIT[:,256:512]
        sgemm_kernel<128, 128, 8, 8, 8><<<grid, 256>>>(
            mf, mfW, mfb, CRIT + 256, 1024, nullptr, 0,
            BB, HH, AD, 0, 0, 0, 0, 0);
        // mf2_enc -> CRIT[:,512:768]
        sgemm_kernel<128, 128, 8, 8, 8><<<grid, 256>>>(
            mf2, mf2W, mf2b, CRIT + 512, 1024, nullptr, 0,
            BB, HH, AD2, 0, 0, 0, 0, 0);
        // sel = SENC @ WSEL (no bias, no activation)
        sgemm_kernel<128, 128, 8, 8, 8><<<grid, 256>>>(
            SENC, WSEL, nullptr, SEL, 256, nullptr, 0,
            BB, HH, HH, /*act_from=*/HH, 0, 0, 0, 0);
    }

    // 4) attention -> CRIT[:,768:1024]
    attention_kernel<<<(BB * HEADS) / 8, 256>>>(SEL, KV, CRIT);

    // 5) h1 = lrelu(CRIT @ W1 + b1)
    {
        dim3 grid(HH / 128, BB / 128, 1);
        sgemm_kernel<128, 128, 8, 8, 8><<<grid, 256>>>(
            CRIT, W1, b1, H1, HH, nullptr, 0,
            BB, HH, 4 * HH, 0, 0, 0, 0, 0);
    }

    // 6) out = H1 @ W2 + b2   (N = 64 -> smaller tile config)
    {
        dim3 grid(ODIM / 64, BB / 64, 1);
        sgemm_kernel<64, 64, 16, 4, 4><<<grid, 256>>>(
            H1, W2, b2, out, ODIM, nullptr, 0,
            BB, ODIM, HH, /*act_from=*/ODIM, 0, 0, 0, 0);
    }
}

// round 3
// speedup vs baseline: 2.8451x; 2.8451x over previous
#include <cuda_runtime.h>
#include <cuda_bf16.h>
#include <cstdint>

#define BB   16384
#define NOTH 31
#define IDIM 192

// ---------------------------------------------------------------------------
// Scratch (__device__ globals; no cudaMalloc allowed)
// ---------------------------------------------------------------------------
__device__ float g_SA  [(long)NOTH * BB * 256];    // encoded others (fp32)
__device__ float g_VALS[(long)NOTH * BB * 256];    // vals, col = e*64+d
__device__ float g_Q   [(long)BB * 1024];          // q, col = e*256+h
__device__ float g_CRIT[(long)BB * 1024];          // [s_enc|mf|mf2|other]
__device__ float g_H1  [(long)BB * 256];

// packed bf16 hi/lo swizzled weight images
__device__ __nv_bfloat16 g_PencW[(long)NOTH * 2 * 192 * 256];
__device__ __nv_bfloat16 g_PWv  [2 * 256 * 256];
__device__ __nv_bfloat16 g_PsW  [2 * 128 * 256];
__device__ __nv_bfloat16 g_PmfW [2 * 64 * 256];
__device__ __nv_bfloat16 g_Pmf2W[2 * 64 * 256];
__device__ __nv_bfloat16 g_PM   [2 * 256 * 1024];
__device__ __nv_bfloat16 g_PW1  [2 * 1024 * 256];
__device__ __nv_bfloat16 g_PW2  [2 * 256 * 64];

// ---------------------------------------------------------------------------
// helpers
// ---------------------------------------------------------------------------
__device__ __forceinline__ void ldsm4(uint32_t* f, uint32_t addr) {
    asm volatile("ldmatrix.sync.aligned.m8n8.x4.shared.b16 {%0,%1,%2,%3}, [%4];"
                 : "=r"(f[0]), "=r"(f[1]), "=r"(f[2]), "=r"(f[3]) : "r"(addr));
}
__device__ __forceinline__ void ldsm4t(uint32_t* f, uint32_t addr) {
    asm volatile("ldmatrix.sync.aligned.m8n8.x4.trans.shared.b16 {%0,%1,%2,%3}, [%4];"
                 : "=r"(f[0]), "=r"(f[1]), "=r"(f[2]), "=r"(f[3]) : "r"(addr));
}
__device__ __forceinline__ void mma16816(float* c, const uint32_t* a, const uint32_t* b) {
    asm volatile("mma.sync.aligned.m16n8k16.row.col.f32.bf16.bf16.f32 "
                 "{%0,%1,%2,%3}, {%4,%5,%6,%7}, {%8,%9}, {%0,%1,%2,%3};"
                 : "+f"(c[0]), "+f"(c[1]), "+f"(c[2]), "+f"(c[3])
                 : "r"(a[0]), "r"(a[1]), "r"(a[2]), "r"(a[3]), "r"(b[0]), "r"(b[1]));
}
__device__ __forceinline__ float wredsum(float v) {
#pragma unroll
    for (int o = 16; o; o >>= 1) v += __shfl_xor_sync(0xffffffffu, v, o);
    return v;
}
__device__ __forceinline__ float wredmax(float v) {
#pragma unroll
    for (int o = 16; o; o >>= 1) v = fmaxf(v, __shfl_xor_sync(0xffffffffu, v, o));
    return v;
}

// pack one element (k, n) of a K x N weight into the hi/lo swizzled image
__device__ __forceinline__ void pack_store(__nv_bfloat16* dst, int K, int BNp,
                                           int k, int n, float v) {
    int ntile = n / BNp, nn = n % BNp, kc = k >> 5, kk = k & 31, c = nn >> 3;
    long img = ((long)ntile * (K >> 5) + kc) * (64L * BNp);
    long off = img + (long)kk * BNp + (long)((c ^ (kk & 7)) << 3) + (nn & 7);
    __nv_bfloat16 hb = __float2bfloat16_rn(v);
    __nv_bfloat16 lb = __float2bfloat16_rn(v - __bfloat162float(hb));
    dst[off] = hb;
    dst[off + 32L * BNp] = lb;
}

// ---------------------------------------------------------------------------
// packers
// ---------------------------------------------------------------------------
__global__ void packB_kernel(const float* __restrict__ W, __nv_bfloat16* __restrict__ dst,
                             int K, int N, int BNp) {
    long total = (long)K * N;
    long i = (long)blockIdx.x * 256 + threadIdx.x;
    if (i >= total) return;
    W   += (long)blockIdx.z * total;
    dst += (long)blockIdx.z * 2 * total;
    int k = (int)(i / N), n = (int)(i % N);
    pack_store(dst, K, BNp, k, n, W[i]);
}

// Wv (4,256,64) -> B[k=h][n=e*64+d], K=256, N=256, BN=128
__global__ void packWv_kernel(const float* __restrict__ Wv) {
    int i = blockIdx.x * 256 + threadIdx.x;   // 0..65535
    int k = i >> 8, n = i & 255;
    int e = n >> 6, d = n & 63;
    pack_store(g_PWv, 256, 128, k, n, Wv[((long)e * 256 + k) * 64 + d]);
}

// Mcat[k=h1][n=e*256+h2] = 0.125 * sum_d Wsel[e][h1][d]*Wk[e][h2][d], then pack
__global__ void packM_kernel(const float* __restrict__ Wsel, const float* __restrict__ Wk) {
    int n = blockIdx.x;          // 0..1023
    int h1 = threadIdx.x;        // 0..255
    int e = n >> 8, h2 = n & 255;
    const float* ws = Wsel + ((long)e * 256 + h1) * 64;
    const float* wk = Wk   + ((long)e * 256 + h2) * 64;
    float acc = 0.f;
#pragma unroll 8
    for (int d = 0; d < 64; d++) acc += ws[d] * wk[d];
    pack_store(g_PM, 256, 128, h1, n, acc * 0.125f);
}

// ---------------------------------------------------------------------------
// bf16-split mma.sync GEMM: C[128 x BN per CTA] = act(A @ B + bias)
//   A fp32 [M x K] row-major (split to hi/lo in the loader)
//   B pre-packed hi/lo swizzled images (per n-tile, per 32-k chunk)
//   3 passes: Ah*Bh + Ah*Bl + Al*Bh
// ---------------------------------------------------------------------------
template <int BN, int ACT>
__global__ void __launch_bounds__(256)
mma_gemm(const float* __restrict__ A, long strideA, int lda,
         const __nv_bfloat16* __restrict__ Bp, long strideB,
         const float* __restrict__ bias, long strideBias,
         float* __restrict__ C, long strideC, int ldc, int K)
{
    constexpr int WN = BN / 2;        // warp N extent (4 M-warps x 2 N-warps)
    constexpr int NT = WN / 8;        // n-tiles per warp
    constexpr int NG = WN / 16;       // ldmatrix x4 groups per warp
    constexpr int BROWB = BN * 2;     // bytes per B smem row
    constexpr int BBYTES = 32 * BN * 2;
    constexpr int BCOPY = (2 * BBYTES) / (256 * 16);

    __shared__ __align__(16) unsigned char sm[16384 + 2 * BBYTES];
    const uint32_t sAhi = (uint32_t)__cvta_generic_to_shared(sm);
    const uint32_t sAlo = sAhi + 8192;
    const uint32_t sBhi = sAhi + 16384;
    const uint32_t sBlo = sBhi + BBYTES;

    const int tid = threadIdx.x, lane = tid & 31, w = tid >> 5;
    const int wm = (w & 3) * 32;
    const int wn = (w >> 2) * WN;
    const int z = blockIdx.z;

    A += (long)z * strideA + (long)blockIdx.y * 128 * lda;
    Bp += (long)z * strideB + ((long)blockIdx.x * (K >> 5)) * (64L * BN);
    if (bias) bias += (long)z * strideBias + blockIdx.x * BN;
    C += (long)z * strideC + (long)blockIdx.y * 128 * ldc + blockIdx.x * BN;

    const int r  = tid >> 1;          // A row handled by this thread
    const int cp = (tid & 1) * 2;     // first of 2 chunks (8 floats each)

    float4 aReg[4];
    uint4  bReg[BCOPY];

    auto gload = [&](int it) {
        const float* ag = A + (long)r * lda + it * 32 + cp * 8;
        aReg[0] = ((const float4*)ag)[0];
        aReg[1] = ((const float4*)ag)[1];
        aReg[2] = ((const float4*)ag)[2];
        aReg[3] = ((const float4*)ag)[3];
        const uint4* bg = (const uint4*)(Bp + (long)it * (64L * BN)) + tid;
#pragma unroll
        for (int i = 0; i < BCOPY; i++) bReg[i] = bg[i * 256];
    };

    auto sstore = [&]() {
#pragma unroll
        for (int cc = 0; cc < 2; cc++) {
            const int chunk = cp + cc;
            float v[8];
            float4 f0 = aReg[2 * cc], f1 = aReg[2 * cc + 1];
            v[0]=f0.x; v[1]=f0.y; v[2]=f0.z; v[3]=f0.w;
            v[4]=f1.x; v[5]=f1.y; v[6]=f1.z; v[7]=f1.w;
            uint32_t hp[4], lp[4];
#pragma unroll
            for (int i = 0; i < 4; i++) {
                __nv_bfloat16 h0 = __float2bfloat16_rn(v[2*i]);
                __nv_bfloat16 h1 = __float2bfloat16_rn(v[2*i+1]);
                __nv_bfloat16 l0 = __float2bfloat16_rn(v[2*i]   - __bfloat162float(h0));
                __nv_bfloat16 l1 = __float2bfloat16_rn(v[2*i+1] - __bfloat162float(h1));
                hp[i] = (uint32_t)__bfloat16_as_ushort(h0) | ((uint32_t)__bfloat16_as_ushort(h1) << 16);
                lp[i] = (uint32_t)__bfloat16_as_ushort(l0) | ((uint32_t)__bfloat16_as_ushort(l1) << 16);
            }
            const uint32_t off = r * 64 + ((chunk ^ ((r >> 1) & 3)) << 4);
            asm volatile("st.shared.v4.b32 [%0], {%1,%2,%3,%4};"
                         :: "r"(sAhi + off), "r"(hp[0]), "r"(hp[1]), "r"(hp[2]), "r"(hp[3]));
            asm volatile("st.shared.v4.b32 [%0], {%1,%2,%3,%4};"
                         :: "r"(sAlo + off), "r"(lp[0]), "r"(lp[1]), "r"(lp[2]), "r"(lp[3]));
        }
#pragma unroll
        for (int i = 0; i < BCOPY; i++)
            asm volatile("st.shared.v4.b32 [%0], {%1,%2,%3,%4};"
                         :: "r"(sBhi + tid * 16 + i * 4096),
                            "r"(bReg[i].x), "r"(bReg[i].y), "r"(bReg[i].z), "r"(bReg[i].w));
    };

    float c[2][NT][4];
#pragma unroll
    for (int mt = 0; mt < 2; mt++)
#pragma unroll
        for (int nt = 0; nt < NT; nt++)
#pragma unroll
            for (int i = 0; i < 4; i++) c[mt][nt][i] = 0.f;

    const int nIter = K >> 5;
    gload(0);

    for (int it = 0; it < nIter; it++) {
        if (it) __syncthreads();
        sstore();
        __syncthreads();
        if (it + 1 < nIter) gload(it + 1);

#pragma unroll
        for (int ks = 0; ks < 2; ks++) {
            uint32_t ah[2][4], al[2][4], bh[NG][4], bl[NG][4];
#pragma unroll
            for (int mt = 0; mt < 2; mt++) {
                const int rr = wm + mt * 16 + (lane & 7) + ((lane >> 3) & 1) * 8;
                const int chunk = (ks * 2 + (lane >> 4)) ^ ((rr >> 1) & 3);
                const uint32_t off = rr * 64 + chunk * 16;
                ldsm4(ah[mt], sAhi + off);
                ldsm4(al[mt], sAlo + off);
            }
#pragma unroll
            for (int g = 0; g < NG; g++) {
                const int kk = ks * 16 + (lane & 7) + ((lane >> 3) & 1) * 8;
                const int chunk = (((wn + g * 16) >> 3) + ((lane >> 4) & 1)) ^ (kk & 7);
                const uint32_t off = kk * BROWB + chunk * 16;
                ldsm4t(bh[g], sBhi + off);
                ldsm4t(bl[g], sBlo + off);
            }
#pragma unroll
            for (int mt = 0; mt < 2; mt++)
#pragma unroll
                for (int nt = 0; nt < NT; nt++) {
                    const uint32_t* bhp = &bh[nt >> 1][(nt & 1) * 2];
                    const uint32_t* blp = &bl[nt >> 1][(nt & 1) * 2];
                    mma16816(c[mt][nt], ah[mt], bhp);
                    mma16816(c[mt][nt], ah[mt], blp);
                    mma16816(c[mt][nt], al[mt], bhp);
                }
        }
    }

    // epilogue
#pragma unroll
    for (int mt = 0; mt < 2; mt++) {
        const int row0 = wm + mt * 16 + (lane >> 2);
#pragma unroll
        for (int nt = 0; nt < NT; nt++) {
            const int col = wn + nt * 8 + (lane & 3) * 2;
            const float b0 = bias ? __ldg(bias + col)     : 0.f;
            const float b1 = bias ? __ldg(bias + col + 1) : 0.f;
            float v0 = c[mt][nt][0] + b0, v1 = c[mt][nt][1] + b1;
            float v2 = c[mt][nt][2] + b0, v3 = c[mt][nt][3] + b1;
            if (ACT) {
                v0 = v0 > 0.f ? v0 : 0.01f * v0;
                v1 = v1 > 0.f ? v1 : 0.01f * v1;
                v2 = v2 > 0.f ? v2 : 0.01f * v2;
                v3 = v3 > 0.f ? v3 : 0.01f * v3;
            }
            *(float2*)&C[(long)row0 * ldc + col]       = make_float2(v0, v1);
            *(float2*)&C[(long)(row0 + 8) * ldc + col] = make_float2(v2, v3);
        }
    }
}

// ---------------------------------------------------------------------------
// Attention: warp per b; logits from SA . q (keys never materialized)
// ---------------------------------------------------------------------------
__global__ void __launch_bounds__(256)
attention_kernel(const float* __restrict__ SA, const float* __restrict__ VALS,
                 const float* __restrict__ Q, float* __restrict__ CRIT)
{
    const int lane = threadIdx.x & 31;
    const long b = (long)blockIdx.x * 8 + (threadIdx.x >> 5);

    float q[4][8];
    const float* qb = Q + b * 1024;
#pragma unroll
    for (int e = 0; e < 4; e++)
#pragma unroll
        for (int j = 0; j < 8; j++) q[e][j] = qb[e * 256 + j * 32 + lane];

    float w0 = -1e30f, w1 = -1e30f, w2 = -1e30f, w3 = -1e30f;
    for (int n = 0; n < NOTH; n++) {
        const float* sa = SA + ((long)n * BB + b) * 256;
        float p0 = 0.f, p1 = 0.f, p2 = 0.f, p3 = 0.f;
#pragma unroll
        for (int j = 0; j < 8; j++) {
            const float x = sa[j * 32 + lane];
            p0 += x * q[0][j]; p1 += x * q[1][j];
            p2 += x * q[2][j]; p3 += x * q[3][j];
        }
        p0 = wredsum(p0); p1 = wredsum(p1); p2 = wredsum(p2); p3 = wredsum(p3);
        if (lane == n) { w0 = p0; w1 = p1; w2 = p2; w3 = p3; }
    }

    {
        float m, p, s;
        m = wredmax(w0); p = __expf(w0 - m); s = wredsum(p); w0 = p / s;
        m = wredmax(w1); p = __expf(w1 - m); s = wredsum(p); w1 = p / s;
        m = wredmax(w2); p = __expf(w2 - m); s = wredsum(p); w2 = p / s;
        m = wredmax(w3); p = __expf(w3 - m); s = wredsum(p); w3 = p / s;
    }

    const int e = lane >> 3;
    float acc[8];
#pragma unroll
    for (int i = 0; i < 8; i++) acc[i] = 0.f;

    for (int n = 0; n < NOTH; n++) {
        const float t0 = __shfl_sync(0xffffffffu, w0, n);
        const float t1 = __shfl_sync(0xffffffffu, w1, n);
        const float t2 = __shfl_sync(0xffffffffu, w2, n);
        const float t3 = __shfl_sync(0xffffffffu, w3, n);
        const float wn = (e == 0) ? t0 : (e == 1) ? t1 : (e == 2) ? t2 : t3;
        const float4* v = (const float4*)(VALS + ((long)n * BB + b) * 256 + lane * 8);
        const float4 a0 = v[0], a1 = v[1];
        acc[0] += wn * a0.x; acc[1] += wn * a0.y;
        acc[2] += wn * a0.z; acc[3] += wn * a0.w;
        acc[4] += wn * a1.x; acc[5] += wn * a1.y;
        acc[6] += wn * a1.z; acc[7] += wn * a1.w;
    }

    float* o = CRIT + b * 1024 + 768 + lane * 8;
    *(float4*)o       = make_float4(acc[0], acc[1], acc[2], acc[3]);
    *(float4*)(o + 4) = make_float4(acc[4], acc[5], acc[6], acc[7]);
}

// ---------------------------------------------------------------------------
// Launch
// ---------------------------------------------------------------------------
extern "C" void kernel_launch(void* const* d_in, const int* in_sizes, int n_in,
                              void* d_out, int out_size)
{
    const float* agent = (const float*)d_in[0];
    const float* state = (const float*)d_in[1];
    const float* mf    = (const float*)d_in[2];
    const float* mf2   = (const float*)d_in[3];
    const float* encW  = (const float*)d_in[4];
    const float* encB  = (const float*)d_in[5];
    const float* sW    = (const float*)d_in[6];
    const float* sb    = (const float*)d_in[7];
    const float* mfW   = (const float*)d_in[8];
    const float* mfb   = (const float*)d_in[9];
    const float* mf2W  = (const float*)d_in[10];
    const float* mf2b  = (const float*)d_in[11];
    const float* Wk    = (const float*)d_in[12];
    const float* Wsel  = (const float*)d_in[13];
    const float* Wv    = (const float*)d_in[14];
    const float* bv    = (const float*)d_in[15];
    const float* W1    = (const float*)d_in[16];
    const float* b1    = (const float*)d_in[17];
    const float* W2    = (const float*)d_in[18];
    const float* b2    = (const float*)d_in[19];
    float* out = (float*)d_out;

    float *SA, *VALS, *Q, *CRIT, *H1;
    __nv_bfloat16 *PencW, *PWv, *PsW, *PmfW, *Pmf2W, *PM, *PW1, *PW2;
    cudaGetSymbolAddress((void**)&SA,    g_SA);
    cudaGetSymbolAddress((void**)&VALS,  g_VALS);
    cudaGetSymbolAddress((void**)&Q,     g_Q);
    cudaGetSymbolAddress((void**)&CRIT,  g_CRIT);
    cudaGetSymbolAddress((void**)&H1,    g_H1);
    cudaGetSymbolAddress((void**)&PencW, g_PencW);
    cudaGetSymbolAddress((void**)&PWv,   g_PWv);
    cudaGetSymbolAddress((void**)&PsW,   g_PsW);
    cudaGetSymbolAddress((void**)&PmfW,  g_PmfW);
    cudaGetSymbolAddress((void**)&Pmf2W, g_Pmf2W);
    cudaGetSymbolAddress((void**)&PM,    g_PM);
    cudaGetSymbolAddress((void**)&PW1,   g_PW1);
    cudaGetSymbolAddress((void**)&PW2,   g_PW2);

    // ---- weight packing ----
    packB_kernel<<<dim3(192 * 256 / 256, 1, NOTH), 256>>>(encW + 192 * 256, PencW, 192, 256, 128);
    packB_kernel<<<dim3(128 * 256 / 256, 1, 1), 256>>>(sW,   PsW,   128, 256, 128);
    packB_kernel<<<dim3( 64 * 256 / 256, 1, 1), 256>>>(mfW,  PmfW,   64, 256, 128);
    packB_kernel<<<dim3( 64 * 256 / 256, 1, 1), 256>>>(mf2W, Pmf2W,  64, 256, 128);
    packB_kernel<<<dim3(1024 * 256 / 256, 1, 1), 256>>>(W1,  PW1,  1024, 256, 128);
    packB_kernel<<<dim3(256 * 64 / 256, 1, 1), 256>>>(W2,   PW2,   256,  64,  64);
    packWv_kernel<<<256, 256>>>(Wv);
    packM_kernel<<<1024, 256>>>(Wsel, Wk);

    // ---- encoder: SA[z] = lrelu(agent[z+1] @ encW[z+1] + encB[z+1]) ----
    mma_gemm<128, 1><<<dim3(2, 128, NOTH), 256>>>(
        agent + (long)BB * IDIM, (long)BB * IDIM, IDIM,
        PencW, 2L * 192 * 256, encB + 256, 256,
        SA, (long)BB * 256, 256, 192);

    // ---- vals = lrelu(SA @ Wv' + bv), M = 31*16384 ----
    mma_gemm<128, 1><<<dim3(2, (NOTH * BB) / 128, 1), 256>>>(
        SA, 0, 256, PWv, 0, bv, 0, VALS, 0, 256, 256);

    // ---- small encoders into CRIT ----
    mma_gemm<128, 1><<<dim3(2, 128, 1), 256>>>(state, 0, 128, PsW,   0, sb,   0, CRIT,       0, 1024, 128);
    mma_gemm<128, 1><<<dim3(2, 128, 1), 256>>>(mf,    0,  64, PmfW,  0, mfb,  0, CRIT + 256, 0, 1024,  64);
    mma_gemm<128, 1><<<dim3(2, 128, 1), 256>>>(mf2,   0,  64, Pmf2W, 0, mf2b, 0, CRIT + 512, 0, 1024,  64);

    // ---- q = s_enc @ Mcat (scale folded), N = 1024 ----
    mma_gemm<128, 0><<<dim3(8, 128, 1), 256>>>(
        CRIT, 0, 1024, PM, 0, nullptr, 0, Q, 0, 1024, 256);

    // ---- attention -> CRIT[:, 768:1024] ----
    attention_kernel<<<BB / 8, 256>>>(SA, VALS, Q, CRIT);

    // ---- h1 = lrelu(CRIT @ W1 + b1) ----
    mma_gemm<128, 1><<<dim3(2, 128, 1), 256>>>(
        CRIT, 0, 1024, PW1, 0, b1, 0, H1, 0, 256, 1024);

    // ---- out = H1 @ W2 + b2 ----
    mma_gemm<64, 0><<<dim3(1, 128, 1), 256>>>(
        H1, 0, 256, PW2, 0, b2, 0, out, 0, 64, 256);
}

// round 4
// speedup vs baseline: 3.5335x; 1.2420x over previous
#include <cuda_runtime.h>
#include <cuda_bf16.h>
#include <cstdint>

#define BB   16384
#define NOTH 31
#define IDIM 192

// ---------------------------------------------------------------------------
// Scratch (__device__ globals; no cudaMalloc allowed)
// ---------------------------------------------------------------------------
__device__ float g_SA  [(long)NOTH * BB * 256];    // encoded others (fp32)
__device__ float g_VALS[(long)NOTH * BB * 256];    // vals, col = e*64+d
__device__ float g_Q   [(long)BB * 1024];          // q, col = e*256+h
__device__ float g_CRIT[(long)BB * 1024];          // [s_enc|mf|mf2|other]
__device__ float g_H1  [(long)BB * 256];

// packed bf16 hi/lo swizzled weight images
__device__ __nv_bfloat16 g_PencW[(long)NOTH * 2 * 192 * 256];  // BNp=256 images
__device__ __nv_bfloat16 g_PWv  [2 * 256 * 256];               // BNp=256
__device__ __nv_bfloat16 g_PsW  [2 * 128 * 256];               // BNp=128
__device__ __nv_bfloat16 g_PmfW [2 * 64 * 256];
__device__ __nv_bfloat16 g_Pmf2W[2 * 64 * 256];
__device__ __nv_bfloat16 g_PM   [2 * 256 * 1024];
__device__ __nv_bfloat16 g_PW1  [2 * 1024 * 256];
__device__ __nv_bfloat16 g_PW2  [2 * 256 * 64];

// ---------------------------------------------------------------------------
// helpers
// ---------------------------------------------------------------------------
__device__ __forceinline__ void ldsm4(uint32_t* f, uint32_t addr) {
    asm volatile("ldmatrix.sync.aligned.m8n8.x4.shared.b16 {%0,%1,%2,%3}, [%4];"
                 : "=r"(f[0]), "=r"(f[1]), "=r"(f[2]), "=r"(f[3]) : "r"(addr));
}
__device__ __forceinline__ void ldsm4t(uint32_t* f, uint32_t addr) {
    asm volatile("ldmatrix.sync.aligned.m8n8.x4.trans.shared.b16 {%0,%1,%2,%3}, [%4];"
                 : "=r"(f[0]), "=r"(f[1]), "=r"(f[2]), "=r"(f[3]) : "r"(addr));
}
__device__ __forceinline__ void mma16816(float* c, const uint32_t* a, const uint32_t* b) {
    asm volatile("mma.sync.aligned.m16n8k16.row.col.f32.bf16.bf16.f32 "
                 "{%0,%1,%2,%3}, {%4,%5,%6,%7}, {%8,%9}, {%0,%1,%2,%3};"
                 : "+f"(c[0]), "+f"(c[1]), "+f"(c[2]), "+f"(c[3])
                 : "r"(a[0]), "r"(a[1]), "r"(a[2]), "r"(a[3]), "r"(b[0]), "r"(b[1]));
}
__device__ __forceinline__ void cpa16(uint32_t dst, const void* src) {
    asm volatile("cp.async.cg.shared.global [%0], [%1], 16;" :: "r"(dst), "l"(src) : "memory");
}
__device__ __forceinline__ void cpa_commit() {
    asm volatile("cp.async.commit_group;" ::: "memory");
}
template <int N> __device__ __forceinline__ void cpa_wait() {
    asm volatile("cp.async.wait_group %0;" :: "n"(N) : "memory");
}
__device__ __forceinline__ float wredsum(float v) {
#pragma unroll
    for (int o = 16; o; o >>= 1) v += __shfl_xor_sync(0xffffffffu, v, o);
    return v;
}
__device__ __forceinline__ float wredmax(float v) {
#pragma unroll
    for (int o = 16; o; o >>= 1) v = fmaxf(v, __shfl_xor_sync(0xffffffffu, v, o));
    return v;
}
__device__ __forceinline__ uint32_t bf16pair(float a, float b, float* ra, float* rb) {
    __nv_bfloat16 ha = __float2bfloat16_rn(a), hb = __float2bfloat16_rn(b);
    *ra = a - __bfloat162float(ha);
    *rb = b - __bfloat162float(hb);
    return (uint32_t)__bfloat16_as_ushort(ha) | ((uint32_t)__bfloat16_as_ushort(hb) << 16);
}

// pack one element (k, n) of a K x N weight into the hi/lo swizzled image
__device__ __forceinline__ void pack_store(__nv_bfloat16* dst, int K, int BNp,
                                           int k, int n, float v) {
    int ntile = n / BNp, nn = n % BNp, kc = k >> 5, kk = k & 31, c = nn >> 3;
    long img = ((long)ntile * (K >> 5) + kc) * (64L * BNp);
    long off = img + (long)kk * BNp + (long)((c ^ (kk & 7)) << 3) + (nn & 7);
    __nv_bfloat16 hb = __float2bfloat16_rn(v);
    __nv_bfloat16 lb = __float2bfloat16_rn(v - __bfloat162float(hb));
    dst[off] = hb;
    dst[off + 32L * BNp] = lb;
}

// ---------------------------------------------------------------------------
// packers
// ---------------------------------------------------------------------------
__global__ void packB_kernel(const float* __restrict__ W, __nv_bfloat16* __restrict__ dst,
                             int K, int N, int BNp) {
    long total = (long)K * N;
    long i = (long)blockIdx.x * 256 + threadIdx.x;
    if (i >= total) return;
    W   += (long)blockIdx.z * total;
    dst += (long)blockIdx.z * 2 * total;
    int k = (int)(i / N), n = (int)(i % N);
    pack_store(dst, K, BNp, k, n, W[i]);
}

// Wv (4,256,64) -> B[k=h][n=e*64+d], K=256, N=256, BNp=256
__global__ void packWv_kernel(const float* __restrict__ Wv) {
    int i = blockIdx.x * 256 + threadIdx.x;   // 0..65535
    int k = i >> 8, n = i & 255;
    int e = n >> 6, d = n & 63;
    pack_store(g_PWv, 256, 256, k, n, Wv[((long)e * 256 + k) * 64 + d]);
}

// Mcat[k=h1][n=e*256+h2] = 0.125 * sum_d Wsel[e][h1][d]*Wk[e][h2][d], then pack
__global__ void packM_kernel(const float* __restrict__ Wsel, const float* __restrict__ Wk) {
    int n = blockIdx.x;          // 0..1023
    int h1 = threadIdx.x;        // 0..255
    int e = n >> 8, h2 = n & 255;
    const float* ws = Wsel + ((long)e * 256 + h1) * 64;
    const float* wk = Wk   + ((long)e * 256 + h2) * 64;
    float acc = 0.f;
#pragma unroll 8
    for (int d = 0; d < 64; d++) acc += ws[d] * wk[d];
    pack_store(g_PM, 256, 128, h1, n, acc * 0.125f);
}

// ---------------------------------------------------------------------------
// FUSED encoder + vals kernel.
//   grid (1, BB/128, NOTH), 256 threads, dyn smem 224 KB.
//   Stage 1: SA_tile[128 x 256] = lrelu(agent_tile @ encW_z + encB_z)
//            -> global SA (fp32) and smem hi/lo bf16 image (8 k-chunks)
//   Stage 2: VALS_tile = lrelu(SA_tile @ Wv' + bv) from the smem image.
//   Warp tiling: 2 M-warps x 4 N-warps; per-warp 64 rows x 64 cols.
// ---------------------------------------------------------------------------
__global__ void __launch_bounds__(256, 1)
fused_enc_vals(const float* __restrict__ agent,
               const __nv_bfloat16* __restrict__ PencW,
               const float* __restrict__ encB,
               const __nv_bfloat16* __restrict__ PWv,
               const float* __restrict__ bv,
               float* __restrict__ SA,
               float* __restrict__ VALS)
{
    extern __shared__ __align__(16) unsigned char smx[];
    const uint32_t sA  = (uint32_t)__cvta_generic_to_shared(smx); // 2 x 16 KB
    const uint32_t sB  = sA + 32768;                              // 2 x 32 KB
    const uint32_t sSA = sA + 98304;                              // 8 x 16 KB

    const int tid = threadIdx.x, lane = tid & 31, w = tid >> 5;
    const int wm = (w & 1) * 64, wn = (w >> 1) * 64;
    const int z = blockIdx.z, by = blockIdx.y;

    const float* Ag = agent + ((long)(z + 1) * BB + (long)by * 128) * IDIM;
    const __nv_bfloat16* Be = PencW + (long)z * (2L * 192 * 256);
    const float* biasE = encB + (long)(z + 1) * 256;

    float acc[4][8][4];

    auto zero_acc = [&]() {
#pragma unroll
        for (int mt = 0; mt < 4; mt++)
#pragma unroll
            for (int nt = 0; nt < 8; nt++)
#pragma unroll
                for (int i = 0; i < 4; i++) acc[mt][nt][i] = 0.f;
    };

    auto mma_chunk = [&](uint32_t aB, uint32_t bB) {
#pragma unroll
        for (int ks = 0; ks < 2; ks++) {
            uint32_t bh[4][4], bl[4][4];
            const int kkB = ks * 16 + (lane & 7) + ((lane >> 3) & 1) * 8;
#pragma unroll
            for (int g = 0; g < 4; g++) {
                const int u = (((wn + g * 16) >> 3) + ((lane >> 4) & 1)) ^ (kkB & 7);
                const uint32_t off = (uint32_t)(kkB * 512 + u * 16);
                ldsm4t(bh[g], bB + off);
                ldsm4t(bl[g], bB + 16384 + off);
            }
#pragma unroll
            for (int mt = 0; mt < 4; mt++) {
                const int rr = wm + mt * 16 + (lane & 7) + ((lane >> 3) & 1) * 8;
                const int u = (ks * 2 + (lane >> 4)) ^ ((rr >> 1) & 3);
                const uint32_t off = (uint32_t)(rr * 64 + u * 16);
                uint32_t ah[4], al[4];
                ldsm4(ah, aB + off);
                ldsm4(al, aB + 8192 + off);
#pragma unroll
                for (int nt = 0; nt < 8; nt++) {
                    const uint32_t* bhp = &bh[nt >> 1][(nt & 1) * 2];
                    const uint32_t* blp = &bl[nt >> 1][(nt & 1) * 2];
                    mma16816(acc[mt][nt], ah, bhp);
                    mma16816(acc[mt][nt], ah, blp);
                    mma16816(acc[mt][nt], al, bhp);
                }
            }
        }
    };

    // ---- A staging (agent fp32 -> hi/lo bf16 smem) ----
    const int ar = tid >> 1, acp = (tid & 1) * 2;
    float4 aReg[4];
    auto gloadA = [&](int c) {
        const float* p = Ag + (long)ar * IDIM + c * 32 + acp * 8;
        aReg[0] = ((const float4*)p)[0];
        aReg[1] = ((const float4*)p)[1];
        aReg[2] = ((const float4*)p)[2];
        aReg[3] = ((const float4*)p)[3];
    };
    auto sstoreA = [&](int buf) {
        const uint32_t bse = sA + buf * 16384;
#pragma unroll
        for (int c2 = 0; c2 < 2; c2++) {
            const int chunk = acp + c2;
            float v[8];
            float4 f0 = aReg[2 * c2], f1 = aReg[2 * c2 + 1];
            v[0]=f0.x; v[1]=f0.y; v[2]=f0.z; v[3]=f0.w;
            v[4]=f1.x; v[5]=f1.y; v[6]=f1.z; v[7]=f1.w;
            uint32_t hp[4], lp[4];
#pragma unroll
            for (int i = 0; i < 4; i++) {
                float r0, r1;
                hp[i] = bf16pair(v[2*i], v[2*i+1], &r0, &r1);
                __nv_bfloat16 l0 = __float2bfloat16_rn(r0), l1 = __float2bfloat16_rn(r1);
                lp[i] = (uint32_t)__bfloat16_as_ushort(l0) | ((uint32_t)__bfloat16_as_ushort(l1) << 16);
            }
            const uint32_t off = ar * 64 + ((chunk ^ ((ar >> 1) & 3)) << 4);
            asm volatile("st.shared.v4.b32 [%0], {%1,%2,%3,%4};"
                         :: "r"(bse + off), "r"(hp[0]), "r"(hp[1]), "r"(hp[2]), "r"(hp[3]));
            asm volatile("st.shared.v4.b32 [%0], {%1,%2,%3,%4};"
                         :: "r"(bse + 8192 + off), "r"(lp[0]), "r"(lp[1]), "r"(lp[2]), "r"(lp[3]));
        }
    };

    // ---- B staging (packed global image -> smem, byte-identical) ----
    auto cpaB = [&](const __nv_bfloat16* src, int c, int buf) {
        const __nv_bfloat16* s = src + (long)c * 16384 + tid * 8;
        const uint32_t d = sB + buf * 32768 + tid * 16;
#pragma unroll
        for (int i = 0; i < 8; i++)
            cpa16(d + i * 4096, s + i * 2048);
    };

    // ================= stage 1: encoder (6 k-chunks) =================
    zero_acc();
    gloadA(0);
    cpaB(Be, 0, 0); cpa_commit();

    for (int c = 0; c < 6; c++) {
        sstoreA(c & 1);
        cpa_wait<0>();
        __syncthreads();
        if (c + 1 < 6) { gloadA(c + 1); cpaB(Be, c + 1, (c + 1) & 1); cpa_commit(); }
        mma_chunk(sA + (c & 1) * 16384, sB + (c & 1) * 32768);
    }

    // prefetch first Wv chunk while doing the stage-1 epilogue
    cpaB(PWv, 0, 0); cpa_commit();

    // ---- stage-1 epilogue: bias + lrelu; write SA global + sSA hi/lo ----
    {
        float* SAg = SA + ((long)z * BB + (long)by * 128) * 256;
#pragma unroll
        for (int mt = 0; mt < 4; mt++) {
            const int row0 = wm + mt * 16 + (lane >> 2);
#pragma unroll
            for (int nt = 0; nt < 8; nt++) {
                const int col = wn + nt * 8 + (lane & 3) * 2;
                const float b0 = __ldg(biasE + col), b1 = __ldg(biasE + col + 1);
                float v0 = acc[mt][nt][0] + b0, v1 = acc[mt][nt][1] + b1;
                float v2 = acc[mt][nt][2] + b0, v3 = acc[mt][nt][3] + b1;
                v0 = v0 > 0.f ? v0 : 0.01f * v0;
                v1 = v1 > 0.f ? v1 : 0.01f * v1;
                v2 = v2 > 0.f ? v2 : 0.01f * v2;
                v3 = v3 > 0.f ? v3 : 0.01f * v3;
                *(float2*)&SAg[(long)row0 * 256 + col]       = make_float2(v0, v1);
                *(float2*)&SAg[(long)(row0 + 8) * 256 + col] = make_float2(v2, v3);
                // smem hi/lo image for stage 2
                const int chunk = col >> 5, kk = col & 31, cc = kk >> 3;
#pragma unroll
                for (int rr2 = 0; rr2 < 2; rr2++) {
                    const int row = row0 + rr2 * 8;
                    const float a0 = rr2 ? v2 : v0, a1 = rr2 ? v3 : v1;
                    float r0, r1;
                    const uint32_t hp = bf16pair(a0, a1, &r0, &r1);
                    __nv_bfloat16 l0 = __float2bfloat16_rn(r0), l1 = __float2bfloat16_rn(r1);
                    const uint32_t lp = (uint32_t)__bfloat16_as_ushort(l0) |
                                        ((uint32_t)__bfloat16_as_ushort(l1) << 16);
                    const uint32_t off = sSA + chunk * 16384 + row * 64 +
                                         ((cc ^ ((row >> 1) & 3)) << 4) + (kk & 7) * 2;
                    asm volatile("st.shared.b32 [%0], %1;" :: "r"(off), "r"(hp));
                    asm volatile("st.shared.b32 [%0], %1;" :: "r"(off + 8192), "r"(lp));
                }
            }
        }
    }
    __syncthreads();

    // ================= stage 2: vals (8 k-chunks from sSA) =================
    zero_acc();
    for (int c = 0; c < 8; c++) {
        cpa_wait<0>();
        __syncthreads();
        if (c + 1 < 8) { cpaB(PWv, c + 1, (c + 1) & 1); cpa_commit(); }
        mma_chunk(sSA + c * 16384, sB + (c & 1) * 32768);
    }

    // ---- stage-2 epilogue: bias bv + lrelu -> VALS ----
    {
        float* Vg = VALS + ((long)z * BB + (long)by * 128) * 256;
#pragma unroll
        for (int mt = 0; mt < 4; mt++) {
            const int row0 = wm + mt * 16 + (lane >> 2);
#pragma unroll
            for (int nt = 0; nt < 8; nt++) {
                const int col = wn + nt * 8 + (lane & 3) * 2;
                const float b0 = __ldg(bv + col), b1 = __ldg(bv + col + 1);
                float v0 = acc[mt][nt][0] + b0, v1 = acc[mt][nt][1] + b1;
                float v2 = acc[mt][nt][2] + b0, v3 = acc[mt][nt][3] + b1;
                v0 = v0 > 0.f ? v0 : 0.01f * v0;
                v1 = v1 > 0.f ? v1 : 0.01f * v1;
                v2 = v2 > 0.f ? v2 : 0.01f * v2;
                v3 = v3 > 0.f ? v3 : 0.01f * v3;
                *(float2*)&Vg[(long)row0 * 256 + col]       = make_float2(v0, v1);
                *(float2*)&Vg[(long)(row0 + 8) * 256 + col] = make_float2(v2, v3);
            }
        }
    }
}

// ---------------------------------------------------------------------------
// bf16-split mma.sync GEMM (small stages; unchanged from R3)
// ---------------------------------------------------------------------------
template <int BN, int ACT>
__global__ void __launch_bounds__(256)
mma_gemm(const float* __restrict__ A, long strideA, int lda,
         const __nv_bfloat16* __restrict__ Bp, long strideB,
         const float* __restrict__ bias, long strideBias,
         float* __restrict__ C, long strideC, int ldc, int K)
{
    constexpr int WN = BN / 2;
    constexpr int NT = WN / 8;
    constexpr int NG = WN / 16;
    constexpr int BROWB = BN * 2;
    constexpr int BBYTES = 32 * BN * 2;
    constexpr int BCOPY = (2 * BBYTES) / (256 * 16);

    __shared__ __align__(16) unsigned char sm[16384 + 2 * BBYTES];
    const uint32_t sAhi = (uint32_t)__cvta_generic_to_shared(sm);
    const uint32_t sAlo = sAhi + 8192;
    const uint32_t sBhi = sAhi + 16384;
    const uint32_t sBlo = sBhi + BBYTES;

    const int tid = threadIdx.x, lane = tid & 31, w = tid >> 5;
    const int wm = (w & 3) * 32;
    const int wn = (w >> 2) * WN;
    const int z = blockIdx.z;

    A += (long)z * strideA + (long)blockIdx.y * 128 * lda;
    Bp += (long)z * strideB + ((long)blockIdx.x * (K >> 5)) * (64L * BN);
    if (bias) bias += (long)z * strideBias + blockIdx.x * BN;
    C += (long)z * strideC + (long)blockIdx.y * 128 * ldc + blockIdx.x * BN;

    const int r  = tid >> 1;
    const int cp = (tid & 1) * 2;

    float4 aReg[4];
    uint4  bReg[BCOPY];

    auto gload = [&](int it) {
        const float* ag = A + (long)r * lda + it * 32 + cp * 8;
        aReg[0] = ((const float4*)ag)[0];
        aReg[1] = ((const float4*)ag)[1];
        aReg[2] = ((const float4*)ag)[2];
        aReg[3] = ((const float4*)ag)[3];
        const uint4* bg = (const uint4*)(Bp + (long)it * (64L * BN)) + tid;
#pragma unroll
        for (int i = 0; i < BCOPY; i++) bReg[i] = bg[i * 256];
    };

    auto sstore = [&]() {
#pragma unroll
        for (int cc = 0; cc < 2; cc++) {
            const int chunk = cp + cc;
            float v[8];
            float4 f0 = aReg[2 * cc], f1 = aReg[2 * cc + 1];
            v[0]=f0.x; v[1]=f0.y; v[2]=f0.z; v[3]=f0.w;
            v[4]=f1.x; v[5]=f1.y; v[6]=f1.z; v[7]=f1.w;
            uint32_t hp[4], lp[4];
#pragma unroll
            for (int i = 0; i < 4; i++) {
                float r0, r1;
                hp[i] = bf16pair(v[2*i], v[2*i+1], &r0, &r1);
                __nv_bfloat16 l0 = __float2bfloat16_rn(r0), l1 = __float2bfloat16_rn(r1);
                lp[i] = (uint32_t)__bfloat16_as_ushort(l0) | ((uint32_t)__bfloat16_as_ushort(l1) << 16);
            }
            const uint32_t off = r * 64 + ((chunk ^ ((r >> 1) & 3)) << 4);
            asm volatile("st.shared.v4.b32 [%0], {%1,%2,%3,%4};"
                         :: "r"(sAhi + off), "r"(hp[0]), "r"(hp[1]), "r"(hp[2]), "r"(hp[3]));
            asm volatile("st.shared.v4.b32 [%0], {%1,%2,%3,%4};"
                         :: "r"(sAlo + off), "r"(lp[0]), "r"(lp[1]), "r"(lp[2]), "r"(lp[3]));
        }
#pragma unroll
        for (int i = 0; i < BCOPY; i++)
            asm volatile("st.shared.v4.b32 [%0], {%1,%2,%3,%4};"
                         :: "r"(sBhi + tid * 16 + i * 4096),
                            "r"(bReg[i].x), "r"(bReg[i].y), "r"(bReg[i].z), "r"(bReg[i].w));
    };

    float c[2][NT][4];
#pragma unroll
    for (int mt = 0; mt < 2; mt++)
#pragma unroll
        for (int nt = 0; nt < NT; nt++)
#pragma unroll
            for (int i = 0; i < 4; i++) c[mt][nt][i] = 0.f;

    const int nIter = K >> 5;
    gload(0);

    for (int it = 0; it < nIter; it++) {
        if (it) __syncthreads();
        sstore();
        __syncthreads();
        if (it + 1 < nIter) gload(it + 1);

#pragma unroll
        for (int ks = 0; ks < 2; ks++) {
            uint32_t ah[2][4], al[2][4], bh[NG][4], bl[NG][4];
#pragma unroll
            for (int mt = 0; mt < 2; mt++) {
                const int rr = wm + mt * 16 + (lane & 7) + ((lane >> 3) & 1) * 8;
                const int chunk = (ks * 2 + (lane >> 4)) ^ ((rr >> 1) & 3);
                const uint32_t off = rr * 64 + chunk * 16;
                ldsm4(ah[mt], sAhi + off);
                ldsm4(al[mt], sAlo + off);
            }
#pragma unroll
            for (int g = 0; g < NG; g++) {
                const int kk = ks * 16 + (lane & 7) + ((lane >> 3) & 1) * 8;
                const int chunk = (((wn + g * 16) >> 3) + ((lane >> 4) & 1)) ^ (kk & 7);
                const uint32_t off = kk * BROWB + chunk * 16;
                ldsm4t(bh[g], sBhi + off);
                ldsm4t(bl[g], sBlo + off);
            }
#pragma unroll
            for (int mt = 0; mt < 2; mt++)
#pragma unroll
                for (int nt = 0; nt < NT; nt++) {
                    const uint32_t* bhp = &bh[nt >> 1][(nt & 1) * 2];
                    const uint32_t* blp = &bl[nt >> 1][(nt & 1) * 2];
                    mma16816(c[mt][nt], ah[mt], bhp);
                    mma16816(c[mt][nt], ah[mt], blp);
                    mma16816(c[mt][nt], al[mt], bhp);
                }
        }
    }

#pragma unroll
    for (int mt = 0; mt < 2; mt++) {
        const int row0 = wm + mt * 16 + (lane >> 2);
#pragma unroll
        for (int nt = 0; nt < NT; nt++) {
            const int col = wn + nt * 8 + (lane & 3) * 2;
            const float b0 = bias ? __ldg(bias + col)     : 0.f;
            const float b1 = bias ? __ldg(bias + col + 1) : 0.f;
            float v0 = c[mt][nt][0] + b0, v1 = c[mt][nt][1] + b1;
            float v2 = c[mt][nt][2] + b0, v3 = c[mt][nt][3] + b1;
            if (ACT) {
                v0 = v0 > 0.f ? v0 : 0.01f * v0;
                v1 = v1 > 0.f ? v1 : 0.01f * v1;
                v2 = v2 > 0.f ? v2 : 0.01f * v2;
                v3 = v3 > 0.f ? v3 : 0.01f * v3;
            }
            *(float2*)&C[(long)row0 * ldc + col]       = make_float2(v0, v1);
            *(float2*)&C[(long)(row0 + 8) * ldc + col] = make_float2(v2, v3);
        }
    }
}

// ---------------------------------------------------------------------------
// Attention: warp per b; logits from SA . q (keys never materialized)
// ---------------------------------------------------------------------------
__global__ void __launch_bounds__(256)
attention_kernel(const float* __restrict__ SA, const float* __restrict__ VALS,
                 const float* __restrict__ Q, float* __restrict__ CRIT)
{
    const int lane = threadIdx.x & 31;
    const long b = (long)blockIdx.x * 8 + (threadIdx.x >> 5);

    float q[4][8];
    const float* qb = Q + b * 1024;
#pragma unroll
    for (int e = 0; e < 4; e++)
#pragma unroll
        for (int j = 0; j < 8; j++) q[e][j] = qb[e * 256 + j * 32 + lane];

    float w0 = -1e30f, w1 = -1e30f, w2 = -1e30f, w3 = -1e30f;
    for (int n = 0; n < NOTH; n++) {
        const float* sa = SA + ((long)n * BB + b) * 256;
        float p0 = 0.f, p1 = 0.f, p2 = 0.f, p3 = 0.f;
#pragma unroll
        for (int j = 0; j < 8; j++) {
            const float x = sa[j * 32 + lane];
            p0 += x * q[0][j]; p1 += x * q[1][j];
            p2 += x * q[2][j]; p3 += x * q[3][j];
        }
        p0 = wredsum(p0); p1 = wredsum(p1); p2 = wredsum(p2); p3 = wredsum(p3);
        if (lane == n) { w0 = p0; w1 = p1; w2 = p2; w3 = p3; }
    }

    {
        float m, p, s;
        m = wredmax(w0); p = __expf(w0 - m); s = wredsum(p); w0 = p / s;
        m = wredmax(w1); p = __expf(w1 - m); s = wredsum(p); w1 = p / s;
        m = wredmax(w2); p = __expf(w2 - m); s = wredsum(p); w2 = p / s;
        m = wredmax(w3); p = __expf(w3 - m); s = wredsum(p); w3 = p / s;
    }

    const int e = lane >> 3;
    float acc[8];
#pragma unroll
    for (int i = 0; i < 8; i++) acc[i] = 0.f;

    for (int n = 0; n < NOTH; n++) {
        const float t0 = __shfl_sync(0xffffffffu, w0, n);
        const float t1 = __shfl_sync(0xffffffffu, w1, n);
        const float t2 = __shfl_sync(0xffffffffu, w2, n);
        const float t3 = __shfl_sync(0xffffffffu, w3, n);
        const float wn = (e == 0) ? t0 : (e == 1) ? t1 : (e == 2) ? t2 : t3;
        const float4* v = (const float4*)(VALS + ((long)n * BB + b) * 256 + lane * 8);
        const float4 a0 = v[0], a1 = v[1];
        acc[0] += wn * a0.x; acc[1] += wn * a0.y;
        acc[2] += wn * a0.z; acc[3] += wn * a0.w;
        acc[4] += wn * a1.x; acc[5] += wn * a1.y;
        acc[6] += wn * a1.z; acc[7] += wn * a1.w;
    }

    float* o = CRIT + b * 1024 + 768 + lane * 8;
    *(float4*)o       = make_float4(acc[0], acc[1], acc[2], acc[3]);
    *(float4*)(o + 4) = make_float4(acc[4], acc[5], acc[6], acc[7]);
}

// ---------------------------------------------------------------------------
// Launch
// ---------------------------------------------------------------------------
extern "C" void kernel_launch(void* const* d_in, const int* in_sizes, int n_in,
                              void* d_out, int out_size)
{
    const float* agent = (const float*)d_in[0];
    const float* state = (const float*)d_in[1];
    const float* mf    = (const float*)d_in[2];
    const float* mf2   = (const float*)d_in[3];
    const float* encW  = (const float*)d_in[4];
    const float* encB  = (const float*)d_in[5];
    const float* sW    = (const float*)d_in[6];
    const float* sb    = (const float*)d_in[7];
    const float* mfW   = (const float*)d_in[8];
    const float* mfb   = (const float*)d_in[9];
    const float* mf2W  = (const float*)d_in[10];
    const float* mf2b  = (const float*)d_in[11];
    const float* Wk    = (const float*)d_in[12];
    const float* Wsel  = (const float*)d_in[13];
    const float* Wv    = (const float*)d_in[14];
    const float* bv    = (const float*)d_in[15];
    const float* W1    = (const float*)d_in[16];
    const float* b1    = (const float*)d_in[17];
    const float* W2    = (const float*)d_in[18];
    const float* b2    = (const float*)d_in[19];
    float* out = (float*)d_out;

    float *SA, *VALS, *Q, *CRIT, *H1;
    __nv_bfloat16 *PencW, *PWv, *PsW, *PmfW, *Pmf2W, *PM, *PW1, *PW2;
    cudaGetSymbolAddress((void**)&SA,    g_SA);
    cudaGetSymbolAddress((void**)&VALS,  g_VALS);
    cudaGetSymbolAddress((void**)&Q,     g_Q);
    cudaGetSymbolAddress((void**)&CRIT,  g_CRIT);
    cudaGetSymbolAddress((void**)&H1,    g_H1);
    cudaGetSymbolAddress((void**)&PencW, g_PencW);
    cudaGetSymbolAddress((void**)&PWv,   g_PWv);
    cudaGetSymbolAddress((void**)&PsW,   g_PsW);
    cudaGetSymbolAddress((void**)&PmfW,  g_PmfW);
    cudaGetSymbolAddress((void**)&Pmf2W, g_Pmf2W);
    cudaGetSymbolAddress((void**)&PM,    g_PM);
    cudaGetSymbolAddress((void**)&PW1,   g_PW1);
    cudaGetSymbolAddress((void**)&PW2,   g_PW2);

    const int FUSED_SMEM = 229376;  // 32 KB A + 64 KB B + 128 KB SA image
    cudaFuncSetAttribute(fused_enc_vals, cudaFuncAttributeMaxDynamicSharedMemorySize, FUSED_SMEM);

    // ---- weight packing ----
    packB_kernel<<<dim3(192 * 256 / 256, 1, NOTH), 256>>>(encW + 192 * 256, PencW, 192, 256, 256);
    packB_kernel<<<dim3(128 * 256 / 256, 1, 1), 256>>>(sW,   PsW,   128, 256, 128);
    packB_kernel<<<dim3( 64 * 256 / 256, 1, 1), 256>>>(mfW,  PmfW,   64, 256, 128);
    packB_kernel<<<dim3( 64 * 256 / 256, 1, 1), 256>>>(mf2W, Pmf2W,  64, 256, 128);
    packB_kernel<<<dim3(1024 * 256 / 256, 1, 1), 256>>>(W1,  PW1,  1024, 256, 128);
    packB_kernel<<<dim3(256 * 64 / 256, 1, 1), 256>>>(W2,   PW2,   256,  64,  64);
    packWv_kernel<<<256, 256>>>(Wv);
    packM_kernel<<<1024, 256>>>(Wsel, Wk);

    // ---- small encoders into CRIT ----
    mma_gemm<128, 1><<<dim3(2, 128, 1), 256>>>(state, 0, 128, PsW,   0, sb,   0, CRIT,       0, 1024, 128);
    mma_gemm<128, 1><<<dim3(2, 128, 1), 256>>>(mf,    0,  64, PmfW,  0, mfb,  0, CRIT + 256, 0, 1024,  64);
    mma_gemm<128, 1><<<dim3(2, 128, 1), 256>>>(mf2,   0,  64, Pmf2W, 0, mf2b, 0, CRIT + 512, 0, 1024,  64);

    // ---- q = s_enc @ Mcat (scale folded), N = 1024 ----
    mma_gemm<128, 0><<<dim3(8, 128, 1), 256>>>(
        CRIT, 0, 1024, PM, 0, nullptr, 0, Q, 0, 1024, 256);

    // ---- fused encoder + vals ----
    fused_enc_vals<<<dim3(1, 128, NOTH), 256, FUSED_SMEM>>>(
        agent, PencW, encB, PWv, bv, SA, VALS);

    // ---- attention -> CRIT[:, 768:1024] ----
    attention_kernel<<<BB / 8, 256>>>(SA, VALS, Q, CRIT);

    // ---- h1 = lrelu(CRIT @ W1 + b1) ----
    mma_gemm<128, 1><<<dim3(2, 128, 1), 256>>>(
        CRIT, 0, 1024, PW1, 0, b1, 0, H1, 0, 256, 1024);

    // ---- out = H1 @ W2 + b2 ----
    mma_gemm<64, 0><<<dim3(1, 128, 1), 256>>>(
        H1, 0, 256, PW2, 0, b2, 0, out, 0, 64, 256);
}